// round 8
// baseline (speedup 1.0000x reference)
#include <cuda_runtime.h>
#include <cuda_fp16.h>

#define DIM       33
#define BINS      32
#define NQUAD     17              // g-quads per (b, r0): rows (2j, 2j+1), j in [0,17)
#define NTHREADS  1024
#define NGROUPS   49
#define NCHUNKS   4096            // (4*2048*2048/4) / NTHREADS
#define PLANE4    1048576         // 2048*2048/4
#define NQENT     (DIM*NQUAD*BINS)     // 17952 quads per channel
#define SMEM_BYTES (NQENT * 8)         // 143616 B
#define BSTRIDE_B (NQUAD * BINS * 8)   // 4352 bytes between b-planes

// Persistent channel-split trilinear LUT kernel, g-quad smem layout.
// Quad Q[b][j][r0] (8B) = { half2(L[b][2j][r0],L[b][2j][r0+1]),
//                           half2(L[b][2j+1][r0],L[b][2j+1][r0+1]) }.
// Per pixel per b-side: g0 even -> ONE LDS.64 gives both g-rows' r-pairs;
// g0 odd -> two predicated LDS.32. Inline-PTX predication avoids BSSY/BSYNC.
__global__ __launch_bounds__(NTHREADS, 1)
void lut3d_kernel(const float* __restrict__ x, const float* __restrict__ lut,
                  float* __restrict__ out) {
    extern __shared__ unsigned int sQ[];
    const int ch  = blockIdx.x % 3;
    const int grp = blockIdx.x / 3;

    // Build the quad table for this channel.
    const float* lc = lut + ch * (DIM * DIM * DIM);
    for (int e = threadIdx.x; e < NQENT; e += NTHREADS) {
        int r0 = e & (BINS - 1);
        int j  = (e >> 5) % NQUAD;
        int b  = (e >> 5) / NQUAD;
        int g_lo = 2 * j, g_hi = 2 * j + 1;
        const float* pl = lc + (b * DIM + g_lo) * DIM + r0;
        __half2 lo = __floats2half2_rn(pl[0], pl[1]);
        __half2 hi = __half2(__float2half_rn(0.f), __float2half_rn(0.f));
        if (g_hi < DIM) {
            const float* ph = lc + (b * DIM + g_hi) * DIM + r0;
            hi = __floats2half2_rn(ph[0], ph[1]);
        }
        sQ[e * 2]     = *reinterpret_cast<unsigned int*>(&lo);
        sQ[e * 2 + 1] = *reinterpret_cast<unsigned int*>(&hi);
    }
    __syncthreads();

    const unsigned sbase = (unsigned)__cvta_generic_to_shared(sQ);
    const float4* __restrict__ X = reinterpret_cast<const float4*>(x);
    float4* __restrict__ O       = reinterpret_cast<float4*>(out);

    int c = grp;
    int v = c * NTHREADS + threadIdx.x;
    int base = (v >> 20) * 3 * PLANE4 + (v & (PLANE4 - 1));
    float4 R  = X[base];
    float4 G  = X[base + PLANE4];
    float4 Bv = X[base + 2 * PLANE4];

    while (true) {
        // Software prefetch of the next chunk.
        int cn = c + NGROUPS;
        bool more = (cn < NCHUNKS);
        int basen = 0;
        float4 Rn, Gn, Bn;
        if (more) {
            int vn = cn * NTHREADS + threadIdx.x;
            basen  = (vn >> 20) * 3 * PLANE4 + (vn & (PLANE4 - 1));
            Rn = X[basen];
            Gn = X[basen + PLANE4];
            Bn = X[basen + 2 * PLANE4];
        }

        float rp[4] = {R.x, R.y, R.z, R.w};
        float gp[4] = {G.x, G.y, G.z, G.w};
        float bp[4] = {Bv.x, Bv.y, Bv.z, Bv.w};
        float o[4];
        #pragma unroll
        for (int k = 0; k < 4; k++) {
            float rr = rp[k] * (float)BINS;
            float gg = gp[k] * (float)BINS;
            float bb = bp[k] * (float)BINS;
            // x in [0,1) => floor <= 31; no clamp needed.
            int r0 = __float2int_rd(rr);
            int g0 = __float2int_rd(gg);
            int b0 = __float2int_rd(bb);
            float fr = rr - (float)r0;
            float fg = gg - (float)g0;
            float fb = bb - (float)b0;

            int odd = g0 & 1;
            int j0  = g0 >> 1;
            int j1  = (g0 + 1) >> 1;
            // byte addresses for b-side b0 (b0+1 handled via +BSTRIDE_B imm)
            unsigned a0 = sbase + (((unsigned)(b0 * NQUAD + j0) * BINS + r0) << 3);
            unsigned a1 = sbase + (((unsigned)(b0 * NQUAD + j1) * BINS + r0) << 3);

            unsigned p00, p01, p10, p11;  // r-pairs: (b0,g0),(b0,g0+1),(b1,g0),(b1,g0+1)
            asm volatile(
                "{\n\t"
                ".reg .pred p;\n\t"
                "setp.eq.u32 p, %6, 0;\n\t"
                "@p  ld.shared.v2.u32 {%0, %1}, [%4];\n\t"
                "@!p ld.shared.u32 %0, [%4 + 4];\n\t"
                "@!p ld.shared.u32 %1, [%5];\n\t"
                "@p  ld.shared.v2.u32 {%2, %3}, [%4 + 4352];\n\t"
                "@!p ld.shared.u32 %2, [%4 + 4356];\n\t"
                "@!p ld.shared.u32 %3, [%5 + 4352];\n\t"
                "}"
                : "=r"(p00), "=r"(p01), "=r"(p10), "=r"(p11)
                : "r"(a0), "r"(a1), "r"(odd));

            float2 v00 = __half22float2(*reinterpret_cast<__half2*>(&p00));
            float2 v01 = __half22float2(*reinterpret_cast<__half2*>(&p01));
            float2 v10 = __half22float2(*reinterpret_cast<__half2*>(&p10));
            float2 v11 = __half22float2(*reinterpret_cast<__half2*>(&p11));
            // factored trilinear: 4 r-lerps, 2 g-lerps, 1 b-lerp
            float c00 = fmaf(fr, v00.y - v00.x, v00.x);
            float c01 = fmaf(fr, v01.y - v01.x, v01.x);
            float c10 = fmaf(fr, v10.y - v10.x, v10.x);
            float c11 = fmaf(fr, v11.y - v11.x, v11.x);
            float c0  = fmaf(fg, c01 - c00, c00);
            float c1  = fmaf(fg, c11 - c10, c10);
            o[k] = fmaf(fb, c1 - c0, c0);
        }
        O[base + ch * PLANE4] = make_float4(o[0], o[1], o[2], o[3]);

        if (!more) break;
        c = cn; base = basen; R = Rn; G = Gn; Bv = Bn;
    }
}

extern "C" void kernel_launch(void* const* d_in, const int* in_sizes, int n_in,
                              void* d_out, int out_size) {
    const float* x   = (const float*)d_in[0];
    const float* lut = (const float*)d_in[1];
    // x has 50,331,648 elems; LUT has 107,811. Swap defensively if order differs.
    if (n_in >= 2 && in_sizes[0] < in_sizes[1]) {
        x   = (const float*)d_in[1];
        lut = (const float*)d_in[0];
    }
    cudaFuncSetAttribute((const void*)lut3d_kernel,
                         cudaFuncAttributeMaxDynamicSharedMemorySize, SMEM_BYTES);
    lut3d_kernel<<<3 * NGROUPS, NTHREADS, SMEM_BYTES>>>(x, lut, (float*)d_out);
}